// round 1
// baseline (speedup 1.0000x reference)
#include <cuda_runtime.h>
#include <math.h>

#define LNUM 102
#define LPAD 104
#define NT   128
#define NEG_INF_VAL (-10000.0f)

__global__ __launch_bounds__(NT, 3)
void crf_fwd_kernel(const float* __restrict__ logits,
                    const float* __restrict__ trans,
                    const int*   __restrict__ lens,
                    float* __restrict__ out,
                    int T)
{
    const int b    = blockIdx.x;
    const int j    = threadIdx.x;
    const int lane = j & 31;
    const int warp = j >> 5;

    __shared__ __align__(16) float p_sh[LPAD];
    __shared__ float red[4];

    // ---- Load E[j, :] = exp(transitions[j, :]) into registers (padded to 104) ----
    float4 E[LPAD / 4];
    #pragma unroll
    for (int q = 0; q < LPAD / 4; ++q) {
        float4 v; v.x = v.y = v.z = v.w = 0.0f;
        if (j < LNUM) {
            const float* tr = trans + (size_t)j * LNUM;
            int k = 4 * q;
            if (k + 0 < LNUM) v.x = __expf(tr[k + 0]);
            if (k + 1 < LNUM) v.y = __expf(tr[k + 1]);
            if (k + 2 < LNUM) v.z = __expf(tr[k + 2]);
            if (k + 3 < LNUM) v.w = __expf(tr[k + 3]);
        }
        E[q] = v;
    }

    // zero the shared-pad entries once; only j<LNUM ever writes p_sh afterwards
    if (j >= LNUM && j < LPAD) p_sh[j] = 0.0f;

    // ---- init alpha ----
    float alpha;
    if (j < LNUM) alpha = (j == LNUM - 2) ? 0.0f : NEG_INF_VAL;
    else          alpha = -1e30f;   // neutral for max reductions

    int len = lens[b];
    if (len > T) len = T;
    const float* lg = logits + (size_t)b * T * LNUM;

    __syncthreads();  // p_sh pad init visible before first matvec

    for (int t = 0; t < len; ++t) {
        // --- M = max_k alpha[k] ---
        float m = alpha;
        #pragma unroll
        for (int o = 16; o; o >>= 1)
            m = fmaxf(m, __shfl_xor_sync(0xffffffffu, m, o));
        if (lane == 0) red[warp] = m;
        __syncthreads();                              // A: red ready; prev matvec reads of p_sh done
        const float M = fmaxf(fmaxf(red[0], red[1]), fmaxf(red[2], red[3]));

        // --- p[k] = exp(alpha[k] - M) ---
        if (j < LNUM) p_sh[j] = __expf(alpha - M);
        __syncthreads();                              // B: p_sh ready; red reads done

        // --- y[j] = sum_k E[j,k] * p[k]  (4 accumulators for ILP) ---
        float y0 = 0.f, y1 = 0.f, y2 = 0.f, y3 = 0.f;
        #pragma unroll
        for (int q = 0; q < LPAD / 4; ++q) {
            float4 pv = *reinterpret_cast<const float4*>(&p_sh[4 * q]);
            y0 = fmaf(E[q].x, pv.x, y0);
            y1 = fmaf(E[q].y, pv.y, y1);
            y2 = fmaf(E[q].z, pv.z, y2);
            y3 = fmaf(E[q].w, pv.w, y3);
        }
        const float y = (y0 + y1) + (y2 + y3);

        if (j < LNUM)
            alpha = lg[(size_t)t * LNUM + j] + M + __logf(y);
    }

    // ---- final: alpha += trans[stop, :]; out[b] = logsumexp(alpha) ----
    if (j < LNUM) alpha += trans[(size_t)(LNUM - 1) * LNUM + j];

    float m = alpha;
    #pragma unroll
    for (int o = 16; o; o >>= 1)
        m = fmaxf(m, __shfl_xor_sync(0xffffffffu, m, o));
    if (lane == 0) red[warp] = m;
    __syncthreads();
    const float M = fmaxf(fmaxf(red[0], red[1]), fmaxf(red[2], red[3]));
    __syncthreads();   // red reads done before reuse as sum buffer

    float e = (j < LNUM) ? __expf(alpha - M) : 0.0f;
    #pragma unroll
    for (int o = 16; o; o >>= 1)
        e += __shfl_xor_sync(0xffffffffu, e, o);
    if (lane == 0) red[warp] = e;
    __syncthreads();
    if (j == 0) {
        float s = (red[0] + red[1]) + (red[2] + red[3]);
        out[b] = M + __logf(s);
    }
}

extern "C" void kernel_launch(void* const* d_in, const int* in_sizes, int n_in,
                              void* d_out, int out_size)
{
    const float* logits = (const float*)d_in[0];   // [B, T, L] f32
    const float* trans  = (const float*)d_in[1];   // [L, L]    f32
    const int*   lens   = (const int*)d_in[2];     // [B]       i32
    float*       out    = (float*)d_out;           // [B]       f32

    const int B = in_sizes[2];
    const int L = LNUM;
    const int T = in_sizes[0] / (B * L);

    crf_fwd_kernel<<<B, NT>>>(logits, trans, lens, out, T);
}

// round 2
// speedup vs baseline: 1.4124x; 1.4124x over previous
#include <cuda_runtime.h>
#include <math.h>

#define LNUM 102
#define LPAD 104
#define NPAIR (LPAD / 2)          // 52 packed pairs
#define NT   128
#define MAXB 1024
#define RENORM_MASK 3             // renormalize every 4 steps

__device__ int g_perm[MAXB];

// ---------- packed f32x2 FMA: d = a*b + d (elementwise on 2 floats) ----------
__device__ __forceinline__ void fma2(unsigned long long& d,
                                     unsigned long long a,
                                     unsigned long long b) {
    asm("fma.rn.f32x2 %0, %1, %2, %0;" : "+l"(d) : "l"(a), "l"(b));
}

__device__ __forceinline__ float2 unpack2(unsigned long long u) {
    float2 f;
    asm("mov.b64 {%0, %1}, %2;" : "=f"(f.x), "=f"(f.y) : "l"(u));
    return f;
}

__device__ __forceinline__ unsigned long long pack2(float x, float y) {
    unsigned long long u;
    asm("mov.b64 %0, {%1, %2};" : "=l"(u) : "f"(x), "f"(y));
    return u;
}

// ---------- tiny LPT pre-sort: order batches by descending length ----------
__global__ void sort_kernel(const int* __restrict__ lens, int B) {
    __shared__ int keys[MAXB];
    const int tid = threadIdx.x;
    for (int i = tid; i < MAXB; i += blockDim.x)
        keys[i] = (i < B) ? ((lens[i] << 10) | (MAXB - 1 - i)) : -1;
    __syncthreads();
    for (int k = 2; k <= MAXB; k <<= 1) {
        for (int j = k >> 1; j > 0; j >>= 1) {
            for (int i = tid; i < MAXB; i += blockDim.x) {
                int ixj = i ^ j;
                if (ixj > i) {
                    int a = keys[i], c = keys[ixj];
                    // descending sort
                    bool seg = ((i & k) == 0);
                    if (seg ? (a < c) : (a > c)) { keys[i] = c; keys[ixj] = a; }
                }
            }
            __syncthreads();
        }
    }
    for (int i = tid; i < B; i += blockDim.x)
        g_perm[i] = (MAXB - 1) - (keys[i] & (MAXB - 1));
}

// ---------- main CRF forward, linear-domain with periodic renorm ----------
__global__ __launch_bounds__(NT, 3)
void crf_fwd_kernel(const float* __restrict__ logits,
                    const float* __restrict__ trans,
                    const int*   __restrict__ lens,
                    float* __restrict__ out,
                    int T)
{
    const int b    = g_perm[blockIdx.x];
    const int j    = threadIdx.x;
    const int lane = j & 31;
    const int warp = j >> 5;

    __shared__ __align__(16) float q_sh[2][LPAD];
    __shared__ float red[4];

    // E[j, k] = exp(trans[j, k]) held as 52 packed f32x2 pairs (pads = 0)
    unsigned long long E2[NPAIR];
    #pragma unroll
    for (int m = 0; m < NPAIR; ++m) {
        float a = 0.f, c = 0.f;
        if (j < LNUM) {
            const float* tr = trans + (size_t)j * LNUM;
            int k = 2 * m;
            if (k + 0 < LNUM) a = __expf(tr[k + 0]);
            if (k + 1 < LNUM) c = __expf(tr[k + 1]);
        }
        E2[m] = pack2(a, c);
    }

    // init q = exp(alpha0): 1 at start label, 0 elsewhere (pads 0 in both bufs)
    if (j < LPAD) { q_sh[0][j] = 0.f; q_sh[1][j] = 0.f; }
    float q = 0.f;
    if (j == LNUM - 2) { q = 1.f; }
    if (j < LPAD) q_sh[0][j] = q;

    int len = lens[b];
    if (len > T) len = T;
    const float* lg = logits + (size_t)b * T * LNUM;

    float C = 0.f;      // log normalization accumulator (identical on all threads)
    int   cur = 0;

    // prefetch logit for t=0
    float lgv = (len > 0 && j < LNUM) ? lg[j] : 0.f;

    __syncthreads();

    for (int t = 0; t < len; ++t) {
        const float el = __expf(lgv);
        // prefetch next step's logit (overlaps matvec + barrier)
        const int tn = (t + 1 < len) ? (t + 1) : t;
        const float lgv_n = (j < LNUM) ? lg[(size_t)tn * LNUM + j] : 0.f;

        // y[j] = sum_k E[j,k] * q[k]  — packed f32x2, 4 accumulator chains
        unsigned long long acc[4] = {0ull, 0ull, 0ull, 0ull};
        const ulonglong2* ps = reinterpret_cast<const ulonglong2*>(q_sh[cur]);
        #pragma unroll
        for (int m = 0; m < NPAIR / 2; ++m) {          // 26 LDS.128
            ulonglong2 pv = ps[m];
            fma2(acc[(2 * m)     & 3], E2[2 * m],     pv.x);
            fma2(acc[(2 * m + 1) & 3], E2[2 * m + 1], pv.y);
        }
        float2 a0 = unpack2(acc[0]), a1 = unpack2(acc[1]);
        float2 a2 = unpack2(acc[2]), a3 = unpack2(acc[3]);
        const float y = ((a0.x + a0.y) + (a1.x + a1.y)) +
                        ((a2.x + a2.y) + (a3.x + a3.y));

        if (j < LNUM) q = el * y;                       // q' = exp(logit) ⊙ (E q)

        // periodic renormalization (uniform branch)
        if ((t & RENORM_MASK) == RENORM_MASK) {
            float m = q;                                // q >= 0 everywhere
            #pragma unroll
            for (int o = 16; o; o >>= 1)
                m = fmaxf(m, __shfl_xor_sync(0xffffffffu, m, o));
            if (lane == 0) red[warp] = m;
            __syncthreads();
            const float M = fmaxf(fmaxf(red[0], red[1]), fmaxf(red[2], red[3]));
            q *= __fdividef(1.f, M);
            C += __logf(M);
        }

        if (j < LNUM) q_sh[cur ^ 1][j] = q;
        lgv = lgv_n;
        __syncthreads();
        cur ^= 1;
    }

    // out[b] = C + log( sum_j q[j] * exp(trans[stop, j]) )
    float v = 0.f;
    if (j < LNUM) v = q * __expf(trans[(size_t)(LNUM - 1) * LNUM + j]);
    #pragma unroll
    for (int o = 16; o; o >>= 1)
        v += __shfl_xor_sync(0xffffffffu, v, o);
    if (lane == 0) red[warp] = v;
    __syncthreads();
    if (j == 0) {
        float s = (red[0] + red[1]) + (red[2] + red[3]);
        out[b] = C + logf(s);
    }
}

extern "C" void kernel_launch(void* const* d_in, const int* in_sizes, int n_in,
                              void* d_out, int out_size)
{
    const float* logits = (const float*)d_in[0];   // [B, T, L] f32
    const float* trans  = (const float*)d_in[1];   // [L, L]    f32
    const int*   lens   = (const int*)d_in[2];     // [B]       i32
    float*       out    = (float*)d_out;           // [B]       f32

    const int B = in_sizes[2];
    const int T = in_sizes[0] / (B * LNUM);

    sort_kernel<<<1, MAXB>>>(lens, B);
    crf_fwd_kernel<<<B, NT>>>(logits, trans, lens, out, T);
}